// round 5
// baseline (speedup 1.0000x reference)
#include <cuda_runtime.h>
#include <cuda_bf16.h>
#include <stdint.h>
#include <math.h>

// Problem shape (fixed): B=2, H=16, S=2048, D=64
#define S_LEN 2048
#define DH 64
#define BH_MAX 32
#define BM 128
#define BN 64
#define NT 256

// smem word layout (uint32 units). Row stride 36 words (144B): conflict-free
#define ROW_W 36
#define QT_W (BM * ROW_W)          // 4608 words per Q (hi or lo)
#define TILE_W (BN * ROW_W)        // 2304 words per KV tile
#define KV_BASE_W (2 * QT_W)       // KV stages start after Qh, Ql
#define SMEM_WORDS (KV_BASE_W + 2 * 4 * TILE_W)
#define SMEM_BYTES (SMEM_WORDS * 4)   // 110592 B -> 2 CTAs/SM fits 228KB

// Pre-split packed bf16 hi/lo (one u32 = two bf16 for an even/odd fp32 pair)
__device__ __align__(16) uint32_t g_Qh[BH_MAX * S_LEN * DH / 2];
__device__ __align__(16) uint32_t g_Ql[BH_MAX * S_LEN * DH / 2];
__device__ __align__(16) uint32_t g_Kh[BH_MAX * S_LEN * DH / 2];
__device__ __align__(16) uint32_t g_Kl[BH_MAX * S_LEN * DH / 2];
__device__ __align__(16) uint32_t g_Vh[BH_MAX * S_LEN * DH / 2];
__device__ __align__(16) uint32_t g_Vl[BH_MAX * S_LEN * DH / 2];

__device__ __forceinline__ void split_pack(float x, float y,
                                           uint32_t& hi, uint32_t& lo) {
    __nv_bfloat16 xh = __float2bfloat16(x);
    __nv_bfloat16 yh = __float2bfloat16(y);
    __nv_bfloat16 xl = __float2bfloat16(x - __bfloat162float(xh));
    __nv_bfloat16 yl = __float2bfloat16(y - __bfloat162float(yh));
    hi = (uint32_t)__bfloat16_as_ushort(xh) |
         ((uint32_t)__bfloat16_as_ushort(yh) << 16);
    lo = (uint32_t)__bfloat16_as_ushort(xl) |
         ((uint32_t)__bfloat16_as_ushort(yl) << 16);
}

// ---------------------------------------------------------------------------
// Prep: RoPE(Q,K) + bf16 hi/lo split of Q, K, V. One thread per fp32 pair.
// ---------------------------------------------------------------------------
__global__ void prep_kernel(const float* __restrict__ Q,
                            const float* __restrict__ K,
                            const float* __restrict__ V, int npairs) {
    int idx = blockIdx.x * blockDim.x + threadIdx.x;
    if (idx >= npairs) return;
    int j = idx & 31;
    int s = (idx >> 5) & (S_LEN - 1);
    float div = expf((float)(2 * j) * (-9.210340371976184f / 64.0f));
    float sn, cs;
    sincosf((float)s * div, &sn, &cs);

    float2 q = reinterpret_cast<const float2*>(Q)[idx];
    float2 k = reinterpret_cast<const float2*>(K)[idx];
    float2 v = reinterpret_cast<const float2*>(V)[idx];

    uint32_t hi, lo;
    split_pack(q.x * cs - q.y * sn, q.x * sn + q.y * cs, hi, lo);
    g_Qh[idx] = hi; g_Ql[idx] = lo;
    split_pack(k.x * cs - k.y * sn, k.x * sn + k.y * cs, hi, lo);
    g_Kh[idx] = hi; g_Kl[idx] = lo;
    split_pack(v.x, v.y, hi, lo);
    g_Vh[idx] = hi; g_Vl[idx] = lo;
}

// ---------------------------------------------------------------------------
__device__ __forceinline__ uint32_t smem_u32(const void* p) {
    uint32_t a;
    asm("{ .reg .u64 t; cvta.to.shared.u64 t, %1; cvt.u32.u64 %0, t; }"
        : "=r"(a) : "l"(p));
    return a;
}

__device__ __forceinline__ void cpa16(uint32_t dst, const void* src) {
    asm volatile("cp.async.cg.shared.global [%0], [%1], 16;"
                 :: "r"(dst), "l"(src) : "memory");
}
#define CPA_COMMIT() asm volatile("cp.async.commit_group;" ::: "memory")
#define CPA_WAIT0()  asm volatile("cp.async.wait_group 0;" ::: "memory")

__device__ __forceinline__ void hmma(float* c, const uint32_t* a,
                                     uint32_t b0, uint32_t b1) {
    asm volatile(
        "mma.sync.aligned.m16n8k16.row.col.f32.bf16.bf16.f32 "
        "{%0,%1,%2,%3}, {%4,%5,%6,%7}, {%8,%9}, {%0,%1,%2,%3};"
        : "+f"(c[0]), "+f"(c[1]), "+f"(c[2]), "+f"(c[3])
        : "r"(a[0]), "r"(a[1]), "r"(a[2]), "r"(a[3]), "r"(b0), "r"(b1));
}

__device__ __forceinline__ void ldsm4(uint32_t* r, uint32_t addr) {
    asm volatile(
        "ldmatrix.sync.aligned.m8n8.x4.shared.b16 {%0,%1,%2,%3}, [%4];"
        : "=r"(r[0]), "=r"(r[1]), "=r"(r[2]), "=r"(r[3]) : "r"(addr));
}

__device__ __forceinline__ void ldsm4t(uint32_t* r, uint32_t addr) {
    asm volatile(
        "ldmatrix.sync.aligned.m8n8.x4.trans.shared.b16 {%0,%1,%2,%3}, [%4];"
        : "=r"(r[0]), "=r"(r[1]), "=r"(r[2]), "=r"(r[3]) : "r"(addr));
}

// ---------------------------------------------------------------------------
// HMMA flash attention: Q hi/lo staged in smem (freeing regs for 2 CTAs/SM),
// cp.async double-buffered K/V. 8 warps; warp w owns q-rows [w*16, w*16+16).
// p = exp(s) directly (no online rescale; scores can't overflow fp32).
// ---------------------------------------------------------------------------
__global__ __launch_bounds__(NT, 2)
void attn_mma(float* __restrict__ out) {
    extern __shared__ __align__(16) uint32_t smem[];
    const uint32_t sb = smem_u32(smem);

    const int tid = threadIdx.x;
    const int wid = tid >> 5;
    const int lane = tid & 31;
    const int tig = lane & 3;
    const int grp = lane >> 2;

    const int qi = (int)(gridDim.x - 1 - blockIdx.x);
    const int bh = blockIdx.y;
    const int qbase = qi * BM;
    const size_t poff = (size_t)bh * S_LEN * (DH / 2);
    const uint32_t* Qhg = g_Qh + poff;
    const uint32_t* Qlg = g_Ql + poff;
    const uint32_t* Khg = g_Kh + poff;
    const uint32_t* Klg = g_Kl + poff;
    const uint32_t* Vhg = g_Vh + poff;
    const uint32_t* Vlg = g_Vl + poff;

    const int q0 = qbase + wid * 16 + grp;
    const int q1 = q0 + 8;

    // ---- stage Q hi/lo into smem (once), via cp.async ----
    {
        const uint32_t qh_b = sb;
        const uint32_t ql_b = sb + QT_W * 4;
        #pragma unroll
        for (int it = 0; it < (BM * 8) / NT; it++) {
            int idx = it * NT + tid;
            int r = idx >> 3, c = idx & 7;
            uint32_t doff = (uint32_t)(r * 144 + c * 16);
            size_t so = (size_t)(qbase + r) * 32 + c * 4;
            cpa16(qh_b + doff, Qhg + so);
            cpa16(ql_b + doff, Qlg + so);
        }
        CPA_COMMIT();
    }

    // ldmatrix lane-address components (144B row stride)
    const int arow_l = wid * 16 + ((lane & 7) + ((lane >> 3) & 1) * 8);
    const int acol_l = ((lane >> 4) & 1) * 8;            // Q a-frag
    const int krow_l = ((lane >> 4) & 1) * 8 + (lane & 7);
    const int kcol_l = ((lane >> 3) & 1) * 8;            // K b-frag
    const int vrow_l = ((lane >> 3) & 1) * 8 + (lane & 7);
    const int vcol_l = ((lane >> 4) & 1) * 8;            // V b-frag (trans)

    const uint32_t qh_b = sb;
    const uint32_t ql_b = sb + QT_W * 4;

    float oacc[8][4];
    #pragma unroll
    for (int j = 0; j < 8; j++)
        #pragma unroll
        for (int i = 0; i < 4; i++) oacc[j][i] = 0.0f;
    float lacc0 = 0.0f, lacc1 = 0.0f;

    const int nkt = 2 * qi + 2;

    auto issue_tile = [&](int kt, int st) {
        const uint32_t base = sb + (uint32_t)(KV_BASE_W + st * 4 * TILE_W) * 4;
        const size_t koff = (size_t)kt * BN * 32;
        #pragma unroll
        for (int it = 0; it < (BN * 8) / NT; it++) {
            int idx = it * NT + tid;
            int r = idx >> 3, c = idx & 7;
            uint32_t d0 = base + (uint32_t)(r * 144 + c * 16);
            size_t so = koff + (size_t)r * 32 + c * 4;
            cpa16(d0 + 0u * TILE_W * 4, Khg + so);
            cpa16(d0 + 1u * TILE_W * 4, Klg + so);
            cpa16(d0 + 2u * TILE_W * 4, Vhg + so);
            cpa16(d0 + 3u * TILE_W * 4, Vlg + so);
        }
        CPA_COMMIT();
    };

    issue_tile(0, 0);

    for (int kt = 0; kt < nkt; kt++) {
        const int kbase = kt * BN;
        const int st = kt & 1;

        CPA_WAIT0();
        __syncthreads();
        if (kt + 1 < nkt) issue_tile(kt + 1, st ^ 1);

        const uint32_t kvb = sb + (uint32_t)(KV_BASE_W + st * 4 * TILE_W) * 4;
        const uint32_t kh_b = kvb;
        const uint32_t kl_b = kvb + 1u * TILE_W * 4;
        const uint32_t vh_b = kvb + 2u * TILE_W * 4;
        const uint32_t vl_b = kvb + 3u * TILE_W * 4;

        // ---- S = Q K^T (3-term bf16 split), Q a-frags from smem ----
        float sacc[8][4];
        #pragma unroll
        for (int j = 0; j < 8; j++)
            #pragma unroll
            for (int i = 0; i < 4; i++) sacc[j][i] = 0.0f;

        #pragma unroll
        for (int ks = 0; ks < 4; ks++) {
            uint32_t qoff = (uint32_t)(arow_l * 144 + (16 * ks + acol_l) * 2);
            uint32_t qh4[4], ql4[4];
            ldsm4(qh4, qh_b + qoff);
            ldsm4(ql4, ql_b + qoff);
            #pragma unroll
            for (int t = 0; t < 4; t++) {
                uint32_t off = (uint32_t)((16 * t + krow_l) * 144 +
                                          (16 * ks + kcol_l) * 2);
                uint32_t bh4[4], bl4[4];
                ldsm4(bh4, kh_b + off);
                ldsm4(bl4, kl_b + off);
                hmma(sacc[2 * t],     qh4, bh4[0], bh4[1]);
                hmma(sacc[2 * t],     qh4, bl4[0], bl4[1]);
                hmma(sacc[2 * t],     ql4, bh4[0], bh4[1]);
                hmma(sacc[2 * t + 1], qh4, bh4[2], bh4[3]);
                hmma(sacc[2 * t + 1], qh4, bl4[2], bl4[3]);
                hmma(sacc[2 * t + 1], ql4, bh4[2], bh4[3]);
            }
        }

        // ---- p = exp(s), causal mask, row sums ----
        const bool need_mask = (kbase + BN - 1 > qbase + wid * 16);
        #pragma unroll
        for (int j = 0; j < 8; j++) {
            int kv0 = kbase + 8 * j + 2 * tig;
            float p0 = __expf(sacc[j][0]);
            float p1 = __expf(sacc[j][1]);
            float p2 = __expf(sacc[j][2]);
            float p3 = __expf(sacc[j][3]);
            if (need_mask) {
                if (kv0 > q0) p0 = 0.0f;
                if (kv0 + 1 > q0) p1 = 0.0f;
                if (kv0 > q1) p2 = 0.0f;
                if (kv0 + 1 > q1) p3 = 0.0f;
            }
            sacc[j][0] = p0; sacc[j][1] = p1;
            sacc[j][2] = p2; sacc[j][3] = p3;
            lacc0 += p0 + p1;
            lacc1 += p2 + p3;
        }

        // ---- O += P V (3-term bf16 split) ----
        #pragma unroll
        for (int ks = 0; ks < 4; ks++) {
            uint32_t ah[4], al[4];
            split_pack(sacc[2 * ks][0],     sacc[2 * ks][1],     ah[0], al[0]);
            split_pack(sacc[2 * ks][2],     sacc[2 * ks][3],     ah[1], al[1]);
            split_pack(sacc[2 * ks + 1][0], sacc[2 * ks + 1][1], ah[2], al[2]);
            split_pack(sacc[2 * ks + 1][2], sacc[2 * ks + 1][3], ah[3], al[3]);
            #pragma unroll
            for (int t = 0; t < 4; t++) {
                uint32_t off = (uint32_t)((16 * ks + vrow_l) * 144 +
                                          (16 * t + vcol_l) * 2);
                uint32_t bh4[4], bl4[4];
                ldsm4t(bh4, vh_b + off);
                ldsm4t(bl4, vl_b + off);
                hmma(oacc[2 * t],     ah, bh4[0], bh4[1]);
                hmma(oacc[2 * t],     ah, bl4[0], bl4[1]);
                hmma(oacc[2 * t],     al, bh4[0], bh4[1]);
                hmma(oacc[2 * t + 1], ah, bh4[2], bh4[3]);
                hmma(oacc[2 * t + 1], ah, bl4[2], bl4[3]);
                hmma(oacc[2 * t + 1], al, bh4[2], bh4[3]);
            }
        }
    }

    // ---- quad-group row-sum reduce, normalize, store ----
    lacc0 += __shfl_xor_sync(0xffffffffu, lacc0, 1);
    lacc0 += __shfl_xor_sync(0xffffffffu, lacc0, 2);
    lacc1 += __shfl_xor_sync(0xffffffffu, lacc1, 1);
    lacc1 += __shfl_xor_sync(0xffffffffu, lacc1, 2);
    float inv0 = 1.0f / lacc0;
    float inv1 = 1.0f / lacc1;

    const size_t hoff = (size_t)bh * S_LEN * DH;
    float* o0 = out + hoff + (size_t)q0 * DH;
    float* o1 = out + hoff + (size_t)q1 * DH;
    #pragma unroll
    for (int j = 0; j < 8; j++) {
        int c = 8 * j + 2 * tig;
        *(float2*)(o0 + c) = make_float2(oacc[j][0] * inv0, oacc[j][1] * inv0);
        *(float2*)(o1 + c) = make_float2(oacc[j][2] * inv1, oacc[j][3] * inv1);
    }
}

// ---------------------------------------------------------------------------
extern "C" void kernel_launch(void* const* d_in, const int* in_sizes, int n_in,
                              void* d_out, int out_size) {
    const float* Q = (const float*)d_in[0];
    const float* K = (const float*)d_in[1];
    const float* V = (const float*)d_in[2];
    float* O = (float*)d_out;

    int total = in_sizes[0];
    int BH = total / (S_LEN * DH);
    int npairs = total / 2;

    cudaFuncSetAttribute(attn_mma, cudaFuncAttributeMaxDynamicSharedMemorySize,
                         SMEM_BYTES);

    prep_kernel<<<(npairs + 255) / 256, 256>>>(Q, K, V, npairs);

    dim3 grid(S_LEN / BM, BH);
    attn_mma<<<grid, NT, SMEM_BYTES>>>(O);
}

// round 6
// speedup vs baseline: 1.1281x; 1.1281x over previous
#include <cuda_runtime.h>
#include <cuda_fp16.h>
#include <stdint.h>
#include <math.h>

// Problem shape (fixed): B=2, H=16, S=2048, D=64
#define S_LEN 2048
#define DH 64
#define BH_MAX 32
#define BM 128
#define BN 64
#define NT 256
#define LOG2E 1.4426950408889634f

// smem word layout (uint32 units). Row stride 36 words (144B): conflict-free
#define ROW_W 36
#define QT_W (BM * ROW_W)          // 4608 words per Q (hi or lo)
#define TILE_W (BN * ROW_W)        // 2304 words per KV tile
#define KV_BASE_W (2 * QT_W)
#define SMEM_WORDS (KV_BASE_W + 2 * 4 * TILE_W)
#define SMEM_BYTES (SMEM_WORDS * 4)   // 110592 B -> 2 CTAs/SM

#define ONES_H2 0x3C003C00u        // half2(1,1)

// Pre-split packed fp16 hi/lo (one u32 = two fp16 for an even/odd fp32 pair)
__device__ __align__(16) uint32_t g_Qh[BH_MAX * S_LEN * DH / 2];
__device__ __align__(16) uint32_t g_Ql[BH_MAX * S_LEN * DH / 2];
__device__ __align__(16) uint32_t g_Kh[BH_MAX * S_LEN * DH / 2];
__device__ __align__(16) uint32_t g_Kl[BH_MAX * S_LEN * DH / 2];
__device__ __align__(16) uint32_t g_Vh[BH_MAX * S_LEN * DH / 2];
__device__ __align__(16) uint32_t g_Vl[BH_MAX * S_LEN * DH / 2];

__device__ __forceinline__ void split_pack_h(float x, float y,
                                             uint32_t& hi, uint32_t& lo) {
    __half xh = __float2half_rn(x);
    __half yh = __float2half_rn(y);
    __half xl = __float2half_rn(x - __half2float(xh));
    __half yl = __float2half_rn(y - __half2float(yh));
    hi = (uint32_t)__half_as_ushort(xh) |
         ((uint32_t)__half_as_ushort(yh) << 16);
    lo = (uint32_t)__half_as_ushort(xl) |
         ((uint32_t)__half_as_ushort(yl) << 16);
}

// ---------------------------------------------------------------------------
// Prep: RoPE(Q,K), Q pre-scaled by log2(e); fp16 hi/lo split of Q, K, V.
// ---------------------------------------------------------------------------
__global__ void prep_kernel(const float* __restrict__ Q,
                            const float* __restrict__ K,
                            const float* __restrict__ V, int npairs) {
    int idx = blockIdx.x * blockDim.x + threadIdx.x;
    if (idx >= npairs) return;
    int j = idx & 31;
    int s = (idx >> 5) & (S_LEN - 1);
    float div = expf((float)(2 * j) * (-9.210340371976184f / 64.0f));
    float sn, cs;
    sincosf((float)s * div, &sn, &cs);

    float2 q = reinterpret_cast<const float2*>(Q)[idx];
    float2 k = reinterpret_cast<const float2*>(K)[idx];
    float2 v = reinterpret_cast<const float2*>(V)[idx];

    uint32_t hi, lo;
    split_pack_h((q.x * cs - q.y * sn) * LOG2E,
                 (q.x * sn + q.y * cs) * LOG2E, hi, lo);
    g_Qh[idx] = hi; g_Ql[idx] = lo;
    split_pack_h(k.x * cs - k.y * sn, k.x * sn + k.y * cs, hi, lo);
    g_Kh[idx] = hi; g_Kl[idx] = lo;
    split_pack_h(v.x, v.y, hi, lo);
    g_Vh[idx] = hi; g_Vl[idx] = lo;
}

// ---------------------------------------------------------------------------
__device__ __forceinline__ uint32_t smem_u32(const void* p) {
    uint32_t a;
    asm("{ .reg .u64 t; cvta.to.shared.u64 t, %1; cvt.u32.u64 %0, t; }"
        : "=r"(a) : "l"(p));
    return a;
}

__device__ __forceinline__ void cpa16(uint32_t dst, const void* src) {
    asm volatile("cp.async.cg.shared.global [%0], [%1], 16;"
                 :: "r"(dst), "l"(src) : "memory");
}
#define CPA_COMMIT() asm volatile("cp.async.commit_group;" ::: "memory")
#define CPA_WAIT0()  asm volatile("cp.async.wait_group 0;" ::: "memory")

__device__ __forceinline__ void hmma(float* c, const uint32_t* a,
                                     uint32_t b0, uint32_t b1) {
    asm volatile(
        "mma.sync.aligned.m16n8k16.row.col.f32.f16.f16.f32 "
        "{%0,%1,%2,%3}, {%4,%5,%6,%7}, {%8,%9}, {%0,%1,%2,%3};"
        : "+f"(c[0]), "+f"(c[1]), "+f"(c[2]), "+f"(c[3])
        : "r"(a[0]), "r"(a[1]), "r"(a[2]), "r"(a[3]), "r"(b0), "r"(b1));
}

__device__ __forceinline__ void ldsm4(uint32_t* r, uint32_t addr) {
    asm volatile(
        "ldmatrix.sync.aligned.m8n8.x4.shared.b16 {%0,%1,%2,%3}, [%4];"
        : "=r"(r[0]), "=r"(r[1]), "=r"(r[2]), "=r"(r[3]) : "r"(addr));
}

__device__ __forceinline__ void ldsm4t(uint32_t* r, uint32_t addr) {
    asm volatile(
        "ldmatrix.sync.aligned.m8n8.x4.trans.shared.b16 {%0,%1,%2,%3}, [%4];"
        : "=r"(r[0]), "=r"(r[1]), "=r"(r[2]), "=r"(r[3]) : "r"(addr));
}

// pack (lo_val, hi_val) floats -> f16x2 (lo in low half)
__device__ __forceinline__ uint32_t pack_h2(float lo_v, float hi_v) {
    uint32_t r;
    asm volatile("cvt.rn.f16x2.f32 %0, %1, %2;"
                 : "=r"(r) : "f"(hi_v), "f"(lo_v));
    return r;
}

__device__ __forceinline__ uint32_t hexp2_2(uint32_t x) {
    uint32_t r;
    asm volatile("ex2.approx.f16x2 %0, %1;" : "=r"(r) : "r"(x));
    return r;
}

// ---------------------------------------------------------------------------
// fp16 HMMA flash attention with online row-max.
// QK: 3-term fp16 split (scores pre-scaled by log2e). P = exp2(s - m) in
// fp16 (single term). PV: Ph*Vh + Ph*Vl. Row-sum l via ones-column HMMA.
// ---------------------------------------------------------------------------
__global__ __launch_bounds__(NT, 2)
void attn_mma(float* __restrict__ out) {
    extern __shared__ __align__(16) uint32_t smem[];
    const uint32_t sb = smem_u32(smem);

    const int tid = threadIdx.x;
    const int wid = tid >> 5;
    const int lane = tid & 31;
    const int tig = lane & 3;
    const int grp = lane >> 2;

    const int qi = (int)(gridDim.x - 1 - blockIdx.x);
    const int bh = blockIdx.y;
    const int qbase = qi * BM;
    const size_t poff = (size_t)bh * S_LEN * (DH / 2);
    const uint32_t* Qhg = g_Qh + poff;
    const uint32_t* Qlg = g_Ql + poff;
    const uint32_t* Khg = g_Kh + poff;
    const uint32_t* Klg = g_Kl + poff;
    const uint32_t* Vhg = g_Vh + poff;
    const uint32_t* Vlg = g_Vl + poff;

    const int q0 = qbase + wid * 16 + grp;
    const int q1 = q0 + 8;
    const int qmaxw = qbase + wid * 16 + 15;   // last row owned by this warp

    // ---- stage Q hi/lo into smem (once) ----
    {
        const uint32_t qh_b = sb;
        const uint32_t ql_b = sb + QT_W * 4;
        #pragma unroll
        for (int it = 0; it < (BM * 8) / NT; it++) {
            int idx = it * NT + tid;
            int r = idx >> 3, c = idx & 7;
            uint32_t doff = (uint32_t)(r * 144 + c * 16);
            size_t so = (size_t)(qbase + r) * 32 + c * 4;
            cpa16(qh_b + doff, Qhg + so);
            cpa16(ql_b + doff, Qlg + so);
        }
        CPA_COMMIT();
    }

    const int arow_l = wid * 16 + ((lane & 7) + ((lane >> 3) & 1) * 8);
    const int acol_l = ((lane >> 4) & 1) * 8;
    const int krow_l = ((lane >> 4) & 1) * 8 + (lane & 7);
    const int kcol_l = ((lane >> 3) & 1) * 8;
    const int vrow_l = ((lane >> 3) & 1) * 8 + (lane & 7);
    const int vcol_l = ((lane >> 4) & 1) * 8;

    const uint32_t qh_b = sb;
    const uint32_t ql_b = sb + QT_W * 4;

    float oacc[8][4];
    #pragma unroll
    for (int j = 0; j < 8; j++)
        #pragma unroll
        for (int i = 0; i < 4; i++) oacc[j][i] = 0.0f;
    float lo4[4] = {0.0f, 0.0f, 0.0f, 0.0f};
    float mrun0 = -1e30f, mrun1 = -1e30f;

    const int nkt = 2 * qi + 2;

    auto issue_tile = [&](int kt, int st) {
        const uint32_t base = sb + (uint32_t)(KV_BASE_W + st * 4 * TILE_W) * 4;
        const size_t koff = (size_t)kt * BN * 32;
        #pragma unroll
        for (int it = 0; it < (BN * 8) / NT; it++) {
            int idx = it * NT + tid;
            int r = idx >> 3, c = idx & 7;
            uint32_t d0 = base + (uint32_t)(r * 144 + c * 16);
            size_t so = koff + (size_t)r * 32 + c * 4;
            cpa16(d0 + 0u * TILE_W * 4, Khg + so);
            cpa16(d0 + 1u * TILE_W * 4, Klg + so);
            cpa16(d0 + 2u * TILE_W * 4, Vhg + so);
            cpa16(d0 + 3u * TILE_W * 4, Vlg + so);
        }
        CPA_COMMIT();
    };

    issue_tile(0, 0);

    for (int kt = 0; kt < nkt; kt++) {
        const int kbase = kt * BN;
        const int st = kt & 1;

        CPA_WAIT0();
        __syncthreads();
        if (kt + 1 < nkt) issue_tile(kt + 1, st ^ 1);

        if (kbase > qmaxw) continue;   // tile fully masked for this warp

        const uint32_t kvb = sb + (uint32_t)(KV_BASE_W + st * 4 * TILE_W) * 4;
        const uint32_t kh_b = kvb;
        const uint32_t kl_b = kvb + 1u * TILE_W * 4;
        const uint32_t vh_b = kvb + 2u * TILE_W * 4;
        const uint32_t vl_b = kvb + 3u * TILE_W * 4;

        // ---- S = Q K^T (3-term fp16 split), skip fully-masked kv blocks ----
        float sacc[8][4];
        #pragma unroll
        for (int j = 0; j < 8; j++)
            #pragma unroll
            for (int i = 0; i < 4; i++) sacc[j][i] = 0.0f;

        #pragma unroll
        for (int ks = 0; ks < 4; ks++) {
            uint32_t qoff = (uint32_t)(arow_l * 144 + (16 * ks + acol_l) * 2);
            uint32_t qh4[4], ql4[4];
            ldsm4(qh4, qh_b + qoff);
            ldsm4(ql4, ql_b + qoff);
            #pragma unroll
            for (int t = 0; t < 4; t++) {
                if (kbase + 16 * t > qmaxw) continue;  // warp-uniform skip
                uint32_t off = (uint32_t)((16 * t + krow_l) * 144 +
                                          (16 * ks + kcol_l) * 2);
                uint32_t bh4[4], bl4[4];
                ldsm4(bh4, kh_b + off);
                ldsm4(bl4, kl_b + off);
                hmma(sacc[2 * t],     qh4, bh4[0], bh4[1]);
                hmma(sacc[2 * t],     qh4, bl4[0], bl4[1]);
                hmma(sacc[2 * t],     ql4, bh4[0], bh4[1]);
                hmma(sacc[2 * t + 1], qh4, bh4[2], bh4[3]);
                hmma(sacc[2 * t + 1], qh4, bl4[2], bl4[3]);
                hmma(sacc[2 * t + 1], ql4, bh4[2], bh4[3]);
            }
        }

        // ---- causal mask -> -1e30 BEFORE the max (diagonal tiles only) ----
        if (kbase + BN - 1 > qbase + wid * 16) {
            #pragma unroll
            for (int j = 0; j < 8; j++) {
                int kv0 = kbase + 8 * j + 2 * tig;
                if (kv0 > q0)     sacc[j][0] = -1e30f;
                if (kv0 + 1 > q0) sacc[j][1] = -1e30f;
                if (kv0 > q1)     sacc[j][2] = -1e30f;
                if (kv0 + 1 > q1) sacc[j][3] = -1e30f;
            }
        }

        // ---- row max over active blocks, online-max update, rescale ----
        float mx0 = -1e30f, mx1 = -1e30f;
        #pragma unroll
        for (int j = 0; j < 8; j++) {
            if (kbase + 8 * j > qmaxw) continue;       // skipped block (zeros)
            mx0 = fmaxf(mx0, fmaxf(sacc[j][0], sacc[j][1]));
            mx1 = fmaxf(mx1, fmaxf(sacc[j][2], sacc[j][3]));
        }
        mx0 = fmaxf(mx0, __shfl_xor_sync(0xffffffffu, mx0, 1));
        mx0 = fmaxf(mx0, __shfl_xor_sync(0xffffffffu, mx0, 2));
        mx1 = fmaxf(mx1, __shfl_xor_sync(0xffffffffu, mx1, 1));
        mx1 = fmaxf(mx1, __shfl_xor_sync(0xffffffffu, mx1, 2));

        float mn0 = fmaxf(mrun0, mx0);
        float mn1 = fmaxf(mrun1, mx1);
        float al0 = exp2f(mrun0 - mn0);
        float al1 = exp2f(mrun1 - mn1);
        mrun0 = mn0; mrun1 = mn1;

        #pragma unroll
        for (int j = 0; j < 8; j++) {
            oacc[j][0] *= al0; oacc[j][1] *= al0;
            oacc[j][2] *= al1; oacc[j][3] *= al1;
        }
        lo4[0] *= al0; lo4[1] *= al0;
        lo4[2] *= al1; lo4[3] *= al1;

        // ---- fused: p = exp2(s - m) in fp16, l-HMMA, PV HMMAs per ks ----
        #pragma unroll
        for (int ks = 0; ks < 4; ks++) {
            if (kbase + 16 * ks > qmaxw) continue;     // warp-uniform skip
            uint32_t ah[4];
            ah[0] = hexp2_2(pack_h2(sacc[2 * ks][0] - mn0,
                                    sacc[2 * ks][1] - mn0));
            ah[1] = hexp2_2(pack_h2(sacc[2 * ks][2] - mn1,
                                    sacc[2 * ks][3] - mn1));
            ah[2] = hexp2_2(pack_h2(sacc[2 * ks + 1][0] - mn0,
                                    sacc[2 * ks + 1][1] - mn0));
            ah[3] = hexp2_2(pack_h2(sacc[2 * ks + 1][2] - mn1,
                                    sacc[2 * ks + 1][3] - mn1));

            hmma(lo4, ah, ONES_H2, ONES_H2);           // row-sum l

            #pragma unroll
            for (int t = 0; t < 4; t++) {
                uint32_t off = (uint32_t)((16 * ks + vrow_l) * 144 +
                                          (16 * t + vcol_l) * 2);
                uint32_t bh4[4], bl4[4];
                ldsm4t(bh4, vh_b + off);
                ldsm4t(bl4, vl_b + off);
                hmma(oacc[2 * t],     ah, bh4[0], bh4[1]);
                hmma(oacc[2 * t],     ah, bl4[0], bl4[1]);
                hmma(oacc[2 * t + 1], ah, bh4[2], bh4[3]);
                hmma(oacc[2 * t + 1], ah, bl4[2], bl4[3]);
            }
        }
    }

    // ---- normalize and store (l replicated across cols: no shfl needed) ----
    float inv0 = 1.0f / lo4[0];
    float inv1 = 1.0f / lo4[2];

    const size_t hoff = (size_t)bh * S_LEN * DH;
    float* o0 = out + hoff + (size_t)q0 * DH;
    float* o1 = out + hoff + (size_t)q1 * DH;
    #pragma unroll
    for (int j = 0; j < 8; j++) {
        int c = 8 * j + 2 * tig;
        *(float2*)(o0 + c) = make_float2(oacc[j][0] * inv0, oacc[j][1] * inv0);
        *(float2*)(o1 + c) = make_float2(oacc[j][2] * inv1, oacc[j][3] * inv1);
    }
}

// ---------------------------------------------------------------------------
extern "C" void kernel_launch(void* const* d_in, const int* in_sizes, int n_in,
                              void* d_out, int out_size) {
    const float* Q = (const float*)d_in[0];
    const float* K = (const float*)d_in[1];
    const float* V = (const float*)d_in[2];
    float* O = (float*)d_out;

    int total = in_sizes[0];
    int BH = total / (S_LEN * DH);
    int npairs = total / 2;

    cudaFuncSetAttribute(attn_mma, cudaFuncAttributeMaxDynamicSharedMemorySize,
                         SMEM_BYTES);

    prep_kernel<<<(npairs + 255) / 256, 256>>>(Q, K, V, npairs);

    dim3 grid(S_LEN / BM, BH);
    attn_mma<<<grid, NT, SMEM_BYTES>>>(O);
}

// round 7
// speedup vs baseline: 1.1838x; 1.0494x over previous
#include <cuda_runtime.h>
#include <cuda_fp16.h>
#include <stdint.h>
#include <math.h>

// Problem shape (fixed): B=2, H=16, S=2048, D=64
#define S_LEN 2048
#define DH 64
#define BH_MAX 32
#define BM 128
#define BN 64
#define NT 256
#define LOG2E 1.4426950408889634f

// smem: 2 stages x {Kh,Kl,Vh,Vl}, row stride 36 words (144B): conflict-free
#define ROW_W 36
#define TILE_W (BN * ROW_W)               // 2304 words per 64x64 fp16 tile
#define SMEM_WORDS (2 * 4 * TILE_W)
#define SMEM_BYTES (SMEM_WORDS * 4)       // 73728 B

#define ONES_H2 0x3C003C00u               // half2(1,1)

// Pre-split packed fp16 hi/lo (one u32 = two fp16 for an even/odd fp32 pair)
__device__ __align__(16) uint32_t g_Qh[BH_MAX * S_LEN * DH / 2];
__device__ __align__(16) uint32_t g_Ql[BH_MAX * S_LEN * DH / 2];
__device__ __align__(16) uint32_t g_Kh[BH_MAX * S_LEN * DH / 2];
__device__ __align__(16) uint32_t g_Kl[BH_MAX * S_LEN * DH / 2];
__device__ __align__(16) uint32_t g_Vh[BH_MAX * S_LEN * DH / 2];
__device__ __align__(16) uint32_t g_Vl[BH_MAX * S_LEN * DH / 2];

__device__ __forceinline__ void split_pack_h(float x, float y,
                                             uint32_t& hi, uint32_t& lo) {
    __half xh = __float2half_rn(x);
    __half yh = __float2half_rn(y);
    __half xl = __float2half_rn(x - __half2float(xh));
    __half yl = __float2half_rn(y - __half2float(yh));
    hi = (uint32_t)__half_as_ushort(xh) |
         ((uint32_t)__half_as_ushort(yh) << 16);
    lo = (uint32_t)__half_as_ushort(xl) |
         ((uint32_t)__half_as_ushort(yl) << 16);
}

// ---------------------------------------------------------------------------
// Prep: RoPE(Q,K), Q pre-scaled by log2(e); fp16 hi/lo split of Q, K, V.
// ---------------------------------------------------------------------------
__global__ void prep_kernel(const float* __restrict__ Q,
                            const float* __restrict__ K,
                            const float* __restrict__ V, int npairs) {
    int idx = blockIdx.x * blockDim.x + threadIdx.x;
    if (idx >= npairs) return;
    int j = idx & 31;
    int s = (idx >> 5) & (S_LEN - 1);
    float div = expf((float)(2 * j) * (-9.210340371976184f / 64.0f));
    float sn, cs;
    sincosf((float)s * div, &sn, &cs);

    float2 q = reinterpret_cast<const float2*>(Q)[idx];
    float2 k = reinterpret_cast<const float2*>(K)[idx];
    float2 v = reinterpret_cast<const float2*>(V)[idx];

    uint32_t hi, lo;
    split_pack_h((q.x * cs - q.y * sn) * LOG2E,
                 (q.x * sn + q.y * cs) * LOG2E, hi, lo);
    g_Qh[idx] = hi; g_Ql[idx] = lo;
    split_pack_h(k.x * cs - k.y * sn, k.x * sn + k.y * cs, hi, lo);
    g_Kh[idx] = hi; g_Kl[idx] = lo;
    split_pack_h(v.x, v.y, hi, lo);
    g_Vh[idx] = hi; g_Vl[idx] = lo;
}

// ---------------------------------------------------------------------------
__device__ __forceinline__ uint32_t smem_u32(const void* p) {
    uint32_t a;
    asm("{ .reg .u64 t; cvta.to.shared.u64 t, %1; cvt.u32.u64 %0, t; }"
        : "=r"(a) : "l"(p));
    return a;
}

__device__ __forceinline__ void cpa16(uint32_t dst, const void* src) {
    asm volatile("cp.async.cg.shared.global [%0], [%1], 16;"
                 :: "r"(dst), "l"(src) : "memory");
}
#define CPA_COMMIT() asm volatile("cp.async.commit_group;" ::: "memory")
#define CPA_WAIT0()  asm volatile("cp.async.wait_group 0;" ::: "memory")

__device__ __forceinline__ void hmma(float* c, const uint32_t* a,
                                     uint32_t b0, uint32_t b1) {
    asm volatile(
        "mma.sync.aligned.m16n8k16.row.col.f32.f16.f16.f32 "
        "{%0,%1,%2,%3}, {%4,%5,%6,%7}, {%8,%9}, {%0,%1,%2,%3};"
        : "+f"(c[0]), "+f"(c[1]), "+f"(c[2]), "+f"(c[3])
        : "r"(a[0]), "r"(a[1]), "r"(a[2]), "r"(a[3]), "r"(b0), "r"(b1));
}

__device__ __forceinline__ void ldsm4(uint32_t* r, uint32_t addr) {
    asm volatile(
        "ldmatrix.sync.aligned.m8n8.x4.shared.b16 {%0,%1,%2,%3}, [%4];"
        : "=r"(r[0]), "=r"(r[1]), "=r"(r[2]), "=r"(r[3]) : "r"(addr));
}

__device__ __forceinline__ void ldsm4t(uint32_t* r, uint32_t addr) {
    asm volatile(
        "ldmatrix.sync.aligned.m8n8.x4.trans.shared.b16 {%0,%1,%2,%3}, [%4];"
        : "=r"(r[0]), "=r"(r[1]), "=r"(r[2]), "=r"(r[3]) : "r"(addr));
}

__device__ __forceinline__ uint32_t pack_h2(float lo_v, float hi_v) {
    uint32_t r;
    asm volatile("cvt.rn.f16x2.f32 %0, %1, %2;"
                 : "=r"(r) : "f"(hi_v), "f"(lo_v));
    return r;
}

__device__ __forceinline__ uint32_t hexp2_2(uint32_t x) {
    uint32_t r;
    asm volatile("ex2.approx.f16x2 %0, %1;" : "=r"(r) : "r"(x));
    return r;
}

// ---------------------------------------------------------------------------
// fp16 HMMA flash attention, online row-max. Q hi/lo register-resident.
// QK: 3-term fp16 split (Q pre-scaled by log2e). P = exp2(s-m) single fp16
// term. PV: Ph*Vh + Ph*Vl. Row-sum l via ones-column HMMA.
// 1 CTA/SM, high regs for deep LDSM/HMMA pipelining.
// ---------------------------------------------------------------------------
__global__ __launch_bounds__(NT, 1)
void attn_mma(float* __restrict__ out) {
    extern __shared__ __align__(16) uint32_t smem[];
    const uint32_t sb = smem_u32(smem);

    const int tid = threadIdx.x;
    const int wid = tid >> 5;
    const int lane = tid & 31;
    const int tig = lane & 3;
    const int grp = lane >> 2;

    const int qi = (int)(gridDim.x - 1 - blockIdx.x);
    const int bh = blockIdx.y;
    const int qbase = qi * BM;
    const size_t poff = (size_t)bh * S_LEN * (DH / 2);
    const uint32_t* Qhg = g_Qh + poff;
    const uint32_t* Qlg = g_Ql + poff;
    const uint32_t* Khg = g_Kh + poff;
    const uint32_t* Klg = g_Kl + poff;
    const uint32_t* Vhg = g_Vh + poff;
    const uint32_t* Vlg = g_Vl + poff;

    const int q0 = qbase + wid * 16 + grp;
    const int q1 = q0 + 8;
    const int qmaxw = qbase + wid * 16 + 15;

    // ---- Q fragments register-resident (pre-split, pre-scaled) ----
    uint32_t qfh[4][4], qfl[4][4];
    #pragma unroll
    for (int ks = 0; ks < 4; ks++) {
        int w = 8 * ks + tig;
        qfh[ks][0] = Qhg[(size_t)q0 * 32 + w];
        qfh[ks][1] = Qhg[(size_t)q1 * 32 + w];
        qfh[ks][2] = Qhg[(size_t)q0 * 32 + w + 4];
        qfh[ks][3] = Qhg[(size_t)q1 * 32 + w + 4];
        qfl[ks][0] = Qlg[(size_t)q0 * 32 + w];
        qfl[ks][1] = Qlg[(size_t)q1 * 32 + w];
        qfl[ks][2] = Qlg[(size_t)q0 * 32 + w + 4];
        qfl[ks][3] = Qlg[(size_t)q1 * 32 + w + 4];
    }

    const int krow_l = ((lane >> 4) & 1) * 8 + (lane & 7);
    const int kcol_l = ((lane >> 3) & 1) * 8;
    const int vrow_l = ((lane >> 3) & 1) * 8 + (lane & 7);
    const int vcol_l = ((lane >> 4) & 1) * 8;

    float oacc[8][4];
    #pragma unroll
    for (int j = 0; j < 8; j++)
        #pragma unroll
        for (int i = 0; i < 4; i++) oacc[j][i] = 0.0f;
    float lo4[4] = {0.0f, 0.0f, 0.0f, 0.0f};
    float mrun0 = -1e30f, mrun1 = -1e30f;

    const int nkt = 2 * qi + 2;

    auto issue_tile = [&](int kt, int st) {
        const uint32_t base = sb + (uint32_t)(st * 4 * TILE_W) * 4;
        const size_t koff = (size_t)kt * BN * 32;
        #pragma unroll
        for (int it = 0; it < (BN * 8) / NT; it++) {
            int idx = it * NT + tid;
            int r = idx >> 3, c = idx & 7;
            uint32_t d0 = base + (uint32_t)(r * 144 + c * 16);
            size_t so = koff + (size_t)r * 32 + c * 4;
            cpa16(d0 + 0u * TILE_W * 4, Khg + so);
            cpa16(d0 + 1u * TILE_W * 4, Klg + so);
            cpa16(d0 + 2u * TILE_W * 4, Vhg + so);
            cpa16(d0 + 3u * TILE_W * 4, Vlg + so);
        }
        CPA_COMMIT();
    };

    issue_tile(0, 0);

    for (int kt = 0; kt < nkt; kt++) {
        const int kbase = kt * BN;
        const int st = kt & 1;

        CPA_WAIT0();
        __syncthreads();
        if (kt + 1 < nkt) issue_tile(kt + 1, st ^ 1);

        if (kbase > qmaxw) continue;   // tile fully masked for this warp

        const uint32_t kvb = sb + (uint32_t)(st * 4 * TILE_W) * 4;
        const uint32_t kh_b = kvb;
        const uint32_t kl_b = kvb + 1u * TILE_W * 4;
        const uint32_t vh_b = kvb + 2u * TILE_W * 4;
        const uint32_t vl_b = kvb + 3u * TILE_W * 4;

        // ---- S = Q K^T (3-term fp16 split), skip masked 16-col blocks ----
        float sacc[8][4];
        #pragma unroll
        for (int j = 0; j < 8; j++)
            #pragma unroll
            for (int i = 0; i < 4; i++) sacc[j][i] = 0.0f;

        #pragma unroll
        for (int t = 0; t < 4; t++) {
            if (kbase + 16 * t > qmaxw) continue;      // warp-uniform skip
            #pragma unroll
            for (int ks = 0; ks < 4; ks++) {
                uint32_t off = (uint32_t)((16 * t + krow_l) * 144 +
                                          (16 * ks + kcol_l) * 2);
                uint32_t bh4[4], bl4[4];
                ldsm4(bh4, kh_b + off);
                ldsm4(bl4, kl_b + off);
                hmma(sacc[2 * t],     qfh[ks], bh4[0], bh4[1]);
                hmma(sacc[2 * t],     qfh[ks], bl4[0], bl4[1]);
                hmma(sacc[2 * t],     qfl[ks], bh4[0], bh4[1]);
                hmma(sacc[2 * t + 1], qfh[ks], bh4[2], bh4[3]);
                hmma(sacc[2 * t + 1], qfh[ks], bl4[2], bl4[3]);
                hmma(sacc[2 * t + 1], qfl[ks], bh4[2], bh4[3]);
            }
        }

        // ---- causal mask -> -1e30 BEFORE the max (diagonal tiles only) ----
        if (kbase + BN - 1 > qbase + wid * 16) {
            #pragma unroll
            for (int j = 0; j < 8; j++) {
                int kv0 = kbase + 8 * j + 2 * tig;
                if (kv0 > q0)     sacc[j][0] = -1e30f;
                if (kv0 + 1 > q0) sacc[j][1] = -1e30f;
                if (kv0 > q1)     sacc[j][2] = -1e30f;
                if (kv0 + 1 > q1) sacc[j][3] = -1e30f;
            }
        }

        // ---- row max over active blocks, online-max update, rescale ----
        float mx0 = -1e30f, mx1 = -1e30f;
        #pragma unroll
        for (int j = 0; j < 8; j++) {
            if (kbase + 8 * j > qmaxw) continue;
            mx0 = fmaxf(mx0, fmaxf(sacc[j][0], sacc[j][1]));
            mx1 = fmaxf(mx1, fmaxf(sacc[j][2], sacc[j][3]));
        }
        mx0 = fmaxf(mx0, __shfl_xor_sync(0xffffffffu, mx0, 1));
        mx0 = fmaxf(mx0, __shfl_xor_sync(0xffffffffu, mx0, 2));
        mx1 = fmaxf(mx1, __shfl_xor_sync(0xffffffffu, mx1, 1));
        mx1 = fmaxf(mx1, __shfl_xor_sync(0xffffffffu, mx1, 2));

        float mn0 = fmaxf(mrun0, mx0);
        float mn1 = fmaxf(mrun1, mx1);
        float al0 = exp2f(mrun0 - mn0);
        float al1 = exp2f(mrun1 - mn1);
        mrun0 = mn0; mrun1 = mn1;

        #pragma unroll
        for (int j = 0; j < 8; j++) {
            oacc[j][0] *= al0; oacc[j][1] *= al0;
            oacc[j][2] *= al1; oacc[j][3] *= al1;
        }
        lo4[0] *= al0; lo4[1] *= al0;
        lo4[2] *= al1; lo4[3] *= al1;

        // ---- fused: p = exp2(s - m) fp16, l-HMMA, PV HMMAs per ks ----
        #pragma unroll
        for (int ks = 0; ks < 4; ks++) {
            if (kbase + 16 * ks > qmaxw) continue;
            uint32_t ah[4];
            ah[0] = hexp2_2(pack_h2(sacc[2 * ks][0] - mn0,
                                    sacc[2 * ks][1] - mn0));
            ah[1] = hexp2_2(pack_h2(sacc[2 * ks][2] - mn1,
                                    sacc[2 * ks][3] - mn1));
            ah[2] = hexp2_2(pack_h2(sacc[2 * ks + 1][0] - mn0,
                                    sacc[2 * ks + 1][1] - mn0));
            ah[3] = hexp2_2(pack_h2(sacc[2 * ks + 1][2] - mn1,
                                    sacc[2 * ks + 1][3] - mn1));

            hmma(lo4, ah, ONES_H2, ONES_H2);           // row-sum l

            #pragma unroll
            for (int t = 0; t < 4; t++) {
                uint32_t off = (uint32_t)((16 * ks + vrow_l) * 144 +
                                          (16 * t + vcol_l) * 2);
                uint32_t bh4[4], bl4[4];
                ldsm4t(bh4, vh_b + off);
                ldsm4t(bl4, vl_b + off);
                hmma(oacc[2 * t],     ah, bh4[0], bh4[1]);
                hmma(oacc[2 * t],     ah, bl4[0], bl4[1]);
                hmma(oacc[2 * t + 1], ah, bh4[2], bh4[3]);
                hmma(oacc[2 * t + 1], ah, bl4[2], bl4[3]);
            }
        }
    }

    // ---- normalize and store (l replicated across quad lanes) ----
    float inv0 = 1.0f / lo4[0];
    float inv1 = 1.0f / lo4[2];

    const size_t hoff = (size_t)bh * S_LEN * DH;
    float* o0 = out + hoff + (size_t)q0 * DH;
    float* o1 = out + hoff + (size_t)q1 * DH;
    #pragma unroll
    for (int j = 0; j < 8; j++) {
        int c = 8 * j + 2 * tig;
        *(float2*)(o0 + c) = make_float2(oacc[j][0] * inv0, oacc[j][1] * inv0);
        *(float2*)(o1 + c) = make_float2(oacc[j][2] * inv1, oacc[j][3] * inv1);
    }
}

// ---------------------------------------------------------------------------
extern "C" void kernel_launch(void* const* d_in, const int* in_sizes, int n_in,
                              void* d_out, int out_size) {
    const float* Q = (const float*)d_in[0];
    const float* K = (const float*)d_in[1];
    const float* V = (const float*)d_in[2];
    float* O = (float*)d_out;

    int total = in_sizes[0];
    int BH = total / (S_LEN * DH);
    int npairs = total / 2;

    cudaFuncSetAttribute(attn_mma, cudaFuncAttributeMaxDynamicSharedMemorySize,
                         SMEM_BYTES);

    prep_kernel<<<(npairs + 255) / 256, 256>>>(Q, K, V, npairs);

    dim3 grid(S_LEN / BM, BH);
    attn_mma<<<grid, NT, SMEM_BYTES>>>(O);
}